// round 3
// baseline (speedup 1.0000x reference)
#include <cuda_runtime.h>
#include <math.h>

#define D 8
#define HID 64
#define PTS_PER_CTA 4
#define THREADS 256
#define GRID 2048
#define EPSF 1e-4f
#define TWOEPSF 2e-4f

typedef unsigned long long u64;

__device__ __forceinline__ u64 pack2(float lo, float hi) {
    u64 r; asm("mov.b64 %0, {%1, %2};" : "=l"(r) : "f"(lo), "f"(hi)); return r;
}

// XLA llvm_ir::EmitFastTanh with with_fma = true (Eigen/XLA rational approx,
// Horner steps as single fma roundings), clamp +-7.90531110763549805,
// |x| < 0.0004 passthrough of the unclamped input.
__device__ __forceinline__ float xla_tanh(float x) {
    const float kClamp = 7.90531110763549805f;
    float xc = fminf(fmaxf(x, -kClamp), kClamp);
    float x2 = __fmul_rn(xc, xc);
    float num = -2.76076847742355e-16f;
    num = __fmaf_rn(x2, num,  2.00018790482477e-13f);
    num = __fmaf_rn(x2, num, -8.60467152213735e-11f);
    num = __fmaf_rn(x2, num,  5.12229709037114e-08f);
    num = __fmaf_rn(x2, num,  1.48572235717979e-05f);
    num = __fmaf_rn(x2, num,  6.37261928875436e-04f);
    num = __fmaf_rn(x2, num,  4.89352455891786e-03f);
    num = __fmul_rn(xc, num);
    float den = 1.19825839466702e-06f;
    den = __fmaf_rn(x2, den,  1.18534705686654e-04f);
    den = __fmaf_rn(x2, den,  2.26843463243900e-03f);
    den = __fmaf_rn(x2, den,  4.89352518554385e-03f);
    float r = __fdiv_rn(num, den);
    return (fabsf(x) < 0.0004f) ? x : r;
}

// smem float offsets
#define OFF_W2  0
#define OFF_W1  (OFF_W2 + 32768)
#define OFF_B1  (OFF_W1 + 512)
#define OFF_B2  (OFF_B1 + 64)
#define OFF_G   (OFF_B2 + 512)
#define OFF_UV  (OFF_G + 512)
#define OFF_UU  (OFF_UV + 64)
#define OFF_T2  (OFF_UU + 256)
#define OFF_CP  (OFF_T2 + 4096)
#define OFF_CM  (OFF_CP + 2048)
#define OFF_RED (OFF_CM + 2048)
#define SMEM_FLOATS (OFF_RED + 8)
#define SMEM_BYTES (SMEM_FLOATS * 4)

__global__ void __launch_bounds__(THREADS, 1)
rg_kernel(const float* __restrict__ pos, const float* __restrict__ uu_g,
          const float* __restrict__ vv_g, const float* __restrict__ chol,
          const float* __restrict__ W1,  const float* __restrict__ b1,
          const float* __restrict__ W2,  const float* __restrict__ b2,
          float* __restrict__ out)
{
    extern __shared__ float sm[];
    float* W2s = sm + OFF_W2;
    float* W1s = sm + OFF_W1;
    float* b1s = sm + OFF_B1;
    float* b2s = sm + OFF_B2;
    float* gS  = sm + OFF_G;
    float* uvS = sm + OFF_UV;   // [p][u0..7 v0..7]
    float* uuS = sm + OFF_UU;   // [p][i*8+j]
    float* t2s = sm + OFF_T2;   // [p][h][k][+,-]
    float* cps = sm + OFF_CP;   // [p][512]
    float* cms = sm + OFF_CM;
    float* redS= sm + OFF_RED;

    const int tid  = threadIdx.x;
    const int lane = tid & 31;
    const int warp = tid >> 5;
    const int n0   = blockIdx.x * PTS_PER_CTA;

    // ---- stage weights / inputs ----
    for (int i = tid; i < HID * 512; i += THREADS) W2s[i] = W2[i];
    for (int i = tid; i < 512; i += THREADS) { W1s[i] = W1[i]; b2s[i] = b2[i]; }
    if (tid < 64) b1s[tid] = b1[tid];
    if (tid < PTS_PER_CTA * 16) {
        int p = tid >> 4, q = tid & 15;
        uvS[tid] = (q < 8) ? uu_g[(n0 + p) * 8 + q] : vv_g[(n0 + p) * 8 + (q - 8)];
    }
    // metric g = tril(L) tril(L)^T + 1e-6 I (unamplified; any fp32 order ok)
    for (int idx = tid; idx < 512; idx += THREADS) {
        int p = idx >> 6, ij = idx & 63, i = ij >> 3, j = ij & 7;
        int mm = (i < j) ? i : j;
        float acc = (i == j) ? 1e-6f : 0.0f;
        for (int m = 0; m <= mm; ++m)
            acc = fmaf(chol[p * 64 + i * 8 + m], chol[p * 64 + j * 8 + m], acc);
        gS[idx] = acc;
    }
    __syncthreads();
    if (tid < PTS_PER_CTA * 64) {
        int p = tid >> 6, i = (tid >> 3) & 7, j = tid & 7;
        uuS[tid] = uvS[p * 16 + i] * uvS[p * 16 + j];
    }

    // ---- Phase 1: t = fast_tanh((pos +- eps e_k)@W1 + b1), replicated rounding ----
    {
        const int p = warp >> 1;
        const int n = n0 + p;
        float posr[D];
        #pragma unroll
        for (int j = 0; j < D; ++j) posr[j] = pos[n * 8 + j];
        const int h0 = lane, h1 = lane + 32;
        const float bb0 = b1s[h0], bb1 = b1s[h1];
        #pragma unroll
        for (int mm = 0; mm < 8; ++mm) {
            int m = (warp & 1) * 8 + mm;     // m = k*2 + s; s=0 -> +eps, s=1 -> -eps
            int k = m >> 1;
            float sgn = (m & 1) ? -EPSF : EPSF;
            float acc0 = 0.0f, acc1 = 0.0f;
            #pragma unroll
            for (int j = 0; j < D; ++j) {
                float pj = posr[j];
                if (j == k) pj = __fadd_rn(pj, sgn);     // pos + offs, one rounding
                acc0 = fmaf(pj, W1s[j * 64 + h0], acc0); // ascending-j fma chain
                acc1 = fmaf(pj, W1s[j * 64 + h1], acc1);
            }
            float t0 = xla_tanh(__fadd_rn(acc0, bb0));
            float t1 = xla_tanh(__fadd_rn(acc1, bb1));
            t2s[((p * 64 + h0) * 8 + k) * 2 + (m & 1)] = t0;
            t2s[((p * 64 + h1) * 8 + k) * 2 + (m & 1)] = t1;
        }
    }
    __syncthreads();

    // ---- Phase 2: c = t@W2 chains (ascending h), packed +/- via fma.rn.f32x2 ----
    const int p    = warp >> 1;
    const int half = warp & 1;
    const int obase = half * 256 + lane;     // lane owns outputs obase + 32*r

    u64 acc2[8][8];
    #pragma unroll
    for (int k = 0; k < 8; ++k)
        #pragma unroll
        for (int r = 0; r < 8; ++r) acc2[k][r] = 0ull;

    const u64* t2p = reinterpret_cast<const u64*>(t2s) + p * 512;  // [h*8 + k]
    #pragma unroll 8
    for (int h = 0; h < HID; ++h) {
        const float* w2row = W2s + h * 512 + obase;
        u64 w2d[8];
        #pragma unroll
        for (int r = 0; r < 8; ++r) { float w = w2row[r * 32]; w2d[r] = pack2(w, w); }
        u64 tv[8];
        #pragma unroll
        for (int k = 0; k < 8; ++k) tv[k] = t2p[h * 8 + k];
        #pragma unroll
        for (int k = 0; k < 8; ++k)
            #pragma unroll
            for (int r = 0; r < 8; ++r)
                asm("fma.rn.f32x2 %0, %1, %2, %0;"
                    : "+l"(acc2[k][r]) : "l"(tv[k]), "l"(w2d[r]));
    }
    // + b2 (one rounded add per element, as in the reference)
    #pragma unroll
    for (int r = 0; r < 8; ++r) {
        float bb = b2s[obase + r * 32];
        u64 bb2 = pack2(bb, bb);
        #pragma unroll
        for (int k = 0; k < 8; ++k)
            asm("add.rn.f32x2 %0, %1, %2;"
                : "=l"(acc2[k][r]) : "l"(acc2[k][r]), "l"(bb2));
    }

    // ---- Phase 3: per-k symmetrize, FD, contract ----
    float partial = 0.0f;
    const int cp  = tid >> 6;             // compute-role point (same mapping as p)
    const int q0  = (tid & 63) * 8;
    for (int k = 0; k < 8; ++k) {
        #pragma unroll
        for (int r = 0; r < 8; ++r) {
            float clo, chi;
            asm("mov.b64 {%0,%1}, %2;" : "=f"(clo), "=f"(chi) : "l"(acc2[k][r]));
            cps[p * 512 + obase + r * 32] = clo;   // c at +eps
            cms[p * 512 + obase + r * 32] = chi;   // c at -eps
        }
        __syncthreads();
        const float* cpp = cps + cp * 512;
        const float* cmm = cms + cp * 512;
        const float  vk  = uvS[cp * 16 + 8 + k];
        #pragma unroll
        for (int qq = 0; qq < 8; ++qq) {
            int o = q0 + qq;
            int l = o & 7;
            if (l == k) continue;                  // (1 - eye) mask on (k,l)
            int i = o >> 6, j = (o >> 3) & 7;
            int o2 = i * 64 + l * 8 + j;
            float gp = 0.5f * __fadd_rn(cpp[o], cpp[o2]);   // Gamma+ (rounded add)
            float gm = 0.5f * __fadd_rn(cmm[o], cmm[o2]);   // Gamma-
            float dg = __fdiv_rn(__fsub_rn(gp, gm), TWOEPSF);
            float w  = uuS[cp * 64 + i * 8 + j] * uvS[cp * 16 + 8 + l] * vk;
            partial = fmaf(w, dg, partial);
        }
        __syncthreads();
    }

    // ---- reduce 64 threads per point, finalize ----
    #pragma unroll
    for (int s = 16; s; s >>= 1) partial += __shfl_xor_sync(0xffffffffu, partial, s);
    if (lane == 0) redS[warp] = partial;
    __syncthreads();
    if (tid < PTS_PER_CTA) {
        float R = redS[2 * tid] + redS[2 * tid + 1];
        const int n = n0 + tid;
        const float* g = gS + (n & 7) * 64;
        const float* uL = uvS + tid * 16;
        const float* vL = uvS + tid * 16 + 8;
        float guu = 0.0f, gvv = 0.0f, guv = 0.0f;
        #pragma unroll
        for (int i = 0; i < D; ++i) {
            float gu = 0.0f, gv = 0.0f;
            #pragma unroll
            for (int j = 0; j < D; ++j) {
                float ge = g[i * 8 + j];
                gu = fmaf(ge, uL[j], gu);
                gv = fmaf(ge, vL[j], gv);
            }
            guu = fmaf(uL[i], gu, guu);
            gvv = fmaf(vL[i], gv, gvv);
            guv = fmaf(uL[i], gv, guv);
        }
        float den = fmaxf(guu * gvv - guv * guv, 1e-8f);
        out[n] = R / den;
    }
}

extern "C" void kernel_launch(void* const* d_in, const int* in_sizes, int n_in,
                              void* d_out, int out_size)
{
    const float* positions = (const float*)d_in[0];
    const float* u         = (const float*)d_in[1];
    const float* v         = (const float*)d_in[2];
    const float* chol      = (const float*)d_in[3];
    const float* W1        = (const float*)d_in[4];
    const float* b1        = (const float*)d_in[5];
    const float* W2        = (const float*)d_in[6];
    const float* b2        = (const float*)d_in[7];
    float* out = (float*)d_out;

    cudaFuncSetAttribute(rg_kernel, cudaFuncAttributeMaxDynamicSharedMemorySize,
                         SMEM_BYTES);
    rg_kernel<<<GRID, THREADS, SMEM_BYTES>>>(positions, u, v, chol,
                                             W1, b1, W2, b2, out);
}

// round 4
// speedup vs baseline: 2.3123x; 2.3123x over previous
#include <cuda_runtime.h>
#include <math.h>

#define D 8
#define HID 64
#define PTS_PER_CTA 4
#define THREADS 256
#define GRID 2048
#define EPSF 1e-4f
#define TWOEPSF 2e-4f

typedef unsigned long long u64;

__device__ __forceinline__ u64 pack2(float lo, float hi) {
    u64 r; asm("mov.b64 %0, {%1, %2};" : "=l"(r) : "f"(lo), "f"(hi)); return r;
}

// XLA EmitFastTanh (with_fma=true): verified bit-match with reference in R3.
__device__ __forceinline__ float xla_tanh(float x) {
    const float kClamp = 7.90531110763549805f;
    float xc = fminf(fmaxf(x, -kClamp), kClamp);
    float x2 = __fmul_rn(xc, xc);
    float num = -2.76076847742355e-16f;
    num = __fmaf_rn(x2, num,  2.00018790482477e-13f);
    num = __fmaf_rn(x2, num, -8.60467152213735e-11f);
    num = __fmaf_rn(x2, num,  5.12229709037114e-08f);
    num = __fmaf_rn(x2, num,  1.48572235717979e-05f);
    num = __fmaf_rn(x2, num,  6.37261928875436e-04f);
    num = __fmaf_rn(x2, num,  4.89352455891786e-03f);
    num = __fmul_rn(xc, num);
    float den = 1.19825839466702e-06f;
    den = __fmaf_rn(x2, den,  1.18534705686654e-04f);
    den = __fmaf_rn(x2, den,  2.26843463243900e-03f);
    den = __fmaf_rn(x2, den,  4.89352518554385e-03f);
    float r = __fdiv_rn(num, den);
    return (fabsf(x) < 0.0004f) ? x : r;
}

// smem float offsets
#define OFF_W2  0
#define OFF_W1  (OFF_W2 + 32768)
#define OFF_B1  (OFF_W1 + 512)
#define OFF_B2  (OFF_B1 + 64)
#define OFF_G   (OFF_B2 + 512)
#define OFF_UV  (OFF_G + 512)
#define OFF_T2  (OFF_UV + 64)
#define OFF_CP  (OFF_T2 + 4096)
#define OFF_CM  (OFF_CP + 2048)
#define OFF_RED (OFF_CM + 2048)
#define SMEM_FLOATS (OFF_RED + 8)
#define SMEM_BYTES (SMEM_FLOATS * 4)

__global__ void __launch_bounds__(THREADS, 1)
rg_kernel(const float* __restrict__ pos, const float* __restrict__ uu_g,
          const float* __restrict__ vv_g, const float* __restrict__ chol,
          const float* __restrict__ W1,  const float* __restrict__ b1,
          const float* __restrict__ W2,  const float* __restrict__ b2,
          float* __restrict__ out)
{
    extern __shared__ float sm[];
    float* W2s = sm + OFF_W2;
    float* W1s = sm + OFF_W1;
    float* b1s = sm + OFF_B1;
    float* b2s = sm + OFF_B2;
    float* gS  = sm + OFF_G;
    float* uvS = sm + OFF_UV;   // [p][u0..7 v0..7]
    float* t2s = sm + OFF_T2;   // [p][h][k][+,-]
    float* cps = sm + OFF_CP;   // [p][512]  (one k at a time)
    float* cms = sm + OFF_CM;
    float* redS= sm + OFF_RED;

    const int tid  = threadIdx.x;
    const int lane = tid & 31;
    const int warp = tid >> 5;
    const int n0   = blockIdx.x * PTS_PER_CTA;

    // ---- stage weights (vectorized) / inputs ----
    {
        const float4* W2v = (const float4*)W2;
        float4* W2sv = (float4*)W2s;
        #pragma unroll
        for (int it = 0; it < 32; ++it)
            W2sv[tid + it * THREADS] = W2v[tid + it * THREADS];
        if (tid < 128) {
            ((float4*)W1s)[tid] = ((const float4*)W1)[tid];
            ((float4*)b2s)[tid] = ((const float4*)b2)[tid];
        }
        if (tid < 64) b1s[tid] = b1[tid];
        if (tid < PTS_PER_CTA * 16) {
            int p = tid >> 4, q = tid & 15;
            uvS[tid] = (q < 8) ? uu_g[(n0 + p) * 8 + q]
                               : vv_g[(n0 + p) * 8 + (q - 8)];
        }
    }
    // metric g (unamplified; any fp32 order ok)
    for (int idx = tid; idx < 512; idx += THREADS) {
        int p = idx >> 6, ij = idx & 63, i = ij >> 3, j = ij & 7;
        int mm = (i < j) ? i : j;
        float acc = (i == j) ? 1e-6f : 0.0f;
        for (int m = 0; m <= mm; ++m)
            acc = fmaf(chol[p * 64 + i * 8 + m], chol[p * 64 + j * 8 + m], acc);
        gS[idx] = acc;
    }
    __syncthreads();

    // ---- Phase 1: t = fast_tanh((pos +- eps e_k)@W1 + b1), replicated rounding ----
    {
        const int p = warp >> 1;
        const int n = n0 + p;
        float posr[D];
        #pragma unroll
        for (int j = 0; j < D; ++j) posr[j] = pos[n * 8 + j];
        const int h0 = lane, h1 = lane + 32;
        const float bb0 = b1s[h0], bb1 = b1s[h1];
        #pragma unroll
        for (int mm = 0; mm < 8; ++mm) {
            int m = (warp & 1) * 8 + mm;     // m = k*2 + s; s=0 -> +eps, s=1 -> -eps
            int k = m >> 1;
            float sgn = (m & 1) ? -EPSF : EPSF;
            float acc0 = 0.0f, acc1 = 0.0f;
            #pragma unroll
            for (int j = 0; j < D; ++j) {
                float pj = posr[j];
                if (j == k) pj = __fadd_rn(pj, sgn);     // pos + offs, one rounding
                acc0 = fmaf(pj, W1s[j * 64 + h0], acc0); // ascending-j fma chain
                acc1 = fmaf(pj, W1s[j * 64 + h1], acc1);
            }
            float t0 = xla_tanh(__fadd_rn(acc0, bb0));
            float t1 = xla_tanh(__fadd_rn(acc1, bb1));
            t2s[((p * 64 + h0) * 8 + k) * 2 + (m & 1)] = t0;
            t2s[((p * 64 + h1) * 8 + k) * 2 + (m & 1)] = t1;
        }
    }
    __syncthreads();

    // ---- per-thread invariants for phase 3 ----
    const int p     = warp >> 1;
    const int half  = warp & 1;
    const int obase = half * 256 + lane;    // lane owns outputs obase + 32*r
    const int cp    = tid >> 6;             // compute-role point in phase 3
    const int q0    = (tid & 63) * 8;       // 8 consecutive outputs, fixed (i,j)
    const float RECIP = 1.0f / TWOEPSF;     // rn(1/2e-4); <=2ulp dev on dG (safe)
    float wl[8];                            // u_i*u_j*v_l*RECIP
    {
        int i = q0 >> 6, j = (q0 >> 3) & 7;
        float wij = uvS[cp * 16 + i] * uvS[cp * 16 + j] * RECIP;
        #pragma unroll
        for (int l = 0; l < 8; ++l) wl[l] = wij * uvS[cp * 16 + 8 + l];
    }

    float partial = 0.0f;
    const u64* t2p = reinterpret_cast<const u64*>(t2s) + p * 512;  // [h*8 + k]

    #pragma unroll
    for (int g = 0; g < 2; ++g) {           // k-groups {0..3}, {4..7}
        // ---- Phase 2 (group g): c = t@W2, ascending-h fma chains, packed +/- ----
        u64 acc2[4][8];
        #pragma unroll
        for (int kk = 0; kk < 4; ++kk)
            #pragma unroll
            for (int r = 0; r < 8; ++r) acc2[kk][r] = 0ull;

        #pragma unroll 4
        for (int h = 0; h < HID; ++h) {
            const float* w2row = W2s + h * 512 + obase;
            u64 w2d[8];
            #pragma unroll
            for (int r = 0; r < 8; ++r) { float w = w2row[r * 32]; w2d[r] = pack2(w, w); }
            u64 tv[4];
            #pragma unroll
            for (int kk = 0; kk < 4; ++kk) tv[kk] = t2p[h * 8 + g * 4 + kk];
            #pragma unroll
            for (int kk = 0; kk < 4; ++kk)
                #pragma unroll
                for (int r = 0; r < 8; ++r)
                    asm("fma.rn.f32x2 %0, %1, %2, %0;"
                        : "+l"(acc2[kk][r]) : "l"(tv[kk]), "l"(w2d[r]));
        }
        #pragma unroll
        for (int r = 0; r < 8; ++r) {       // + b2, one rounded add per element
            float bb = b2s[obase + r * 32];
            u64 bb2 = pack2(bb, bb);
            #pragma unroll
            for (int kk = 0; kk < 4; ++kk)
                asm("add.rn.f32x2 %0, %1, %2;"
                    : "=l"(acc2[kk][r]) : "l"(acc2[kk][r]), "l"(bb2));
        }

        // ---- Phase 3 (group g): per-k symmetrize, FD, contract ----
        #pragma unroll
        for (int kk = 0; kk < 4; ++kk) {
            const int k = g * 4 + kk;
            #pragma unroll
            for (int r = 0; r < 8; ++r) {
                float clo, chi;
                asm("mov.b64 {%0,%1}, %2;" : "=f"(clo), "=f"(chi) : "l"(acc2[kk][r]));
                cps[p * 512 + obase + r * 32] = clo;   // c at +eps
                cms[p * 512 + obase + r * 32] = chi;   // c at -eps
            }
            __syncthreads();
            const float* cpp = cps + cp * 512;
            const float* cmm = cms + cp * 512;
            const float  vk  = uvS[cp * 16 + 8 + k];
            float sk = 0.0f;
            #pragma unroll
            for (int l = 0; l < 8; ++l) {
                if (l == k) continue;                  // (1 - eye) mask on (k,l)
                int o  = q0 + l;
                int i  = o >> 6, j = (o >> 3) & 7;
                int o2 = i * 64 + l * 8 + j;
                float gp = 0.5f * __fadd_rn(cpp[o], cpp[o2]);   // Gamma+ (rounded)
                float gm = 0.5f * __fadd_rn(cmm[o], cmm[o2]);   // Gamma-
                sk = fmaf(wl[l], __fsub_rn(gp, gm), sk);
            }
            partial = fmaf(vk, sk, partial);
            __syncthreads();
        }
    }

    // ---- reduce 64 threads per point, finalize ----
    #pragma unroll
    for (int s = 16; s; s >>= 1) partial += __shfl_xor_sync(0xffffffffu, partial, s);
    if (lane == 0) redS[warp] = partial;
    __syncthreads();
    if (tid < PTS_PER_CTA) {
        float R = redS[2 * tid] + redS[2 * tid + 1];
        const int n = n0 + tid;
        const float* g = gS + (n & 7) * 64;
        const float* uL = uvS + tid * 16;
        const float* vL = uvS + tid * 16 + 8;
        float guu = 0.0f, gvv = 0.0f, guv = 0.0f;
        #pragma unroll
        for (int i = 0; i < D; ++i) {
            float gu = 0.0f, gv = 0.0f;
            #pragma unroll
            for (int j = 0; j < D; ++j) {
                float ge = g[i * 8 + j];
                gu = fmaf(ge, uL[j], gu);
                gv = fmaf(ge, vL[j], gv);
            }
            guu = fmaf(uL[i], gu, guu);
            gvv = fmaf(vL[i], gv, gvv);
            guv = fmaf(uL[i], gv, guv);
        }
        float den = fmaxf(guu * gvv - guv * guv, 1e-8f);
        out[n] = R / den;
    }
}

extern "C" void kernel_launch(void* const* d_in, const int* in_sizes, int n_in,
                              void* d_out, int out_size)
{
    const float* positions = (const float*)d_in[0];
    const float* u         = (const float*)d_in[1];
    const float* v         = (const float*)d_in[2];
    const float* chol      = (const float*)d_in[3];
    const float* W1        = (const float*)d_in[4];
    const float* b1        = (const float*)d_in[5];
    const float* W2        = (const float*)d_in[6];
    const float* b2        = (const float*)d_in[7];
    float* out = (float*)d_out;

    cudaFuncSetAttribute(rg_kernel, cudaFuncAttributeMaxDynamicSharedMemorySize,
                         SMEM_BYTES);
    rg_kernel<<<GRID, THREADS, SMEM_BYTES>>>(positions, u, v, chol,
                                             W1, b1, W2, b2, out);
}

// round 5
// speedup vs baseline: 2.8996x; 1.2539x over previous
#include <cuda_runtime.h>
#include <math.h>

#define D 8
#define HID 64
#define PTS_PER_CTA 8
#define THREADS 512
#define GRID 1024
#define EPSF 1e-4f
#define TWOEPSF 2e-4f

typedef unsigned long long u64;

__device__ __forceinline__ u64 pack2(float lo, float hi) {
    u64 r; asm("mov.b64 %0, {%1, %2};" : "=l"(r) : "f"(lo), "f"(hi)); return r;
}

// XLA EmitFastTanh (with_fma=true): verified bit-match with reference in R3.
__device__ __forceinline__ float xla_tanh(float x) {
    const float kClamp = 7.90531110763549805f;
    float xc = fminf(fmaxf(x, -kClamp), kClamp);
    float x2 = __fmul_rn(xc, xc);
    float num = -2.76076847742355e-16f;
    num = __fmaf_rn(x2, num,  2.00018790482477e-13f);
    num = __fmaf_rn(x2, num, -8.60467152213735e-11f);
    num = __fmaf_rn(x2, num,  5.12229709037114e-08f);
    num = __fmaf_rn(x2, num,  1.48572235717979e-05f);
    num = __fmaf_rn(x2, num,  6.37261928875436e-04f);
    num = __fmaf_rn(x2, num,  4.89352455891786e-03f);
    num = __fmul_rn(xc, num);
    float den = 1.19825839466702e-06f;
    den = __fmaf_rn(x2, den,  1.18534705686654e-04f);
    den = __fmaf_rn(x2, den,  2.26843463243900e-03f);
    den = __fmaf_rn(x2, den,  4.89352518554385e-03f);
    float r = __fdiv_rn(num, den);
    return (fabsf(x) < 0.0004f) ? x : r;
}

// smem float offsets
#define OFF_W2  0
#define OFF_W1  (OFF_W2 + 32768)
#define OFF_B1  (OFF_W1 + 512)
#define OFF_B2  (OFF_B1 + 64)
#define OFF_G   (OFF_B2 + 512)
#define OFF_UV  (OFF_G + 512)           // [p][u0..7 v0..7] : 128
#define OFF_T2  (OFF_UV + 128)          // [p][h][k][+,-]   : 8192
#define OFF_CP  (OFF_T2 + 8192)         // [p][row0..63][9] : 4608 (stride-9 pad)
#define OFF_CM  (OFF_CP + 4608)         // 4608
#define OFF_RED (OFF_CM + 4608)         // 16
#define SMEM_FLOATS (OFF_RED + 16)
#define SMEM_BYTES (SMEM_FLOATS * 4)

__global__ void __launch_bounds__(THREADS, 1)
rg_kernel(const float* __restrict__ pos, const float* __restrict__ uu_g,
          const float* __restrict__ vv_g, const float* __restrict__ chol,
          const float* __restrict__ W1,  const float* __restrict__ b1,
          const float* __restrict__ W2,  const float* __restrict__ b2,
          float* __restrict__ out)
{
    extern __shared__ float sm[];
    float* W2s = sm + OFF_W2;
    float* W1s = sm + OFF_W1;
    float* b1s = sm + OFF_B1;
    float* b2s = sm + OFF_B2;
    float* gS  = sm + OFF_G;
    float* uvS = sm + OFF_UV;
    float* t2s = sm + OFF_T2;
    float* cpsS= sm + OFF_CP;
    float* cmsS= sm + OFF_CM;
    float* redS= sm + OFF_RED;

    const int tid  = threadIdx.x;
    const int lane = tid & 31;
    const int warp = tid >> 5;
    const int n0   = blockIdx.x * PTS_PER_CTA;

    // ---- stage weights (vectorized) / inputs ----
    {
        const float4* W2v = (const float4*)W2;
        float4* W2sv = (float4*)W2s;
        #pragma unroll
        for (int it = 0; it < 16; ++it)
            W2sv[tid + it * THREADS] = W2v[tid + it * THREADS];
        if (tid < 128) {
            ((float4*)W1s)[tid] = ((const float4*)W1)[tid];
            ((float4*)b2s)[tid] = ((const float4*)b2)[tid];
        }
        if (tid < 64) b1s[tid] = b1[tid];
        if (tid < PTS_PER_CTA * 16) {
            int pp = tid >> 4, q = tid & 15;
            uvS[tid] = (q < 8) ? uu_g[(n0 + pp) * 8 + q]
                               : vv_g[(n0 + pp) * 8 + (q - 8)];
        }
    }
    // metric g (unamplified; any fp32 order ok)
    if (tid < 512) {
        int pp = tid >> 6, ij = tid & 63, i = ij >> 3, j = ij & 7;
        int mm = (i < j) ? i : j;
        float acc = (i == j) ? 1e-6f : 0.0f;
        for (int m = 0; m <= mm; ++m)
            acc = fmaf(chol[pp * 64 + i * 8 + m], chol[pp * 64 + j * 8 + m], acc);
        gS[tid] = acc;
    }
    __syncthreads();

    // ---- Phase 1: t = fast_tanh((pos +- eps e_k)@W1 + b1), replicated rounding ----
    {
        const int p = warp >> 1;
        const int n = n0 + p;
        float posr[D];
        #pragma unroll
        for (int j = 0; j < D; ++j) posr[j] = pos[n * 8 + j];
        const int h0 = lane, h1 = lane + 32;
        const float bb0 = b1s[h0], bb1 = b1s[h1];
        #pragma unroll
        for (int mm = 0; mm < 8; ++mm) {
            int m = (warp & 1) * 8 + mm;     // m = k*2 + s; s=0 -> +eps, s=1 -> -eps
            int k = m >> 1;
            float sgn = (m & 1) ? -EPSF : EPSF;
            float acc0 = 0.0f, acc1 = 0.0f;
            #pragma unroll
            for (int j = 0; j < D; ++j) {
                float pj = posr[j];
                if (j == k) pj = __fadd_rn(pj, sgn);     // pos + offs, one rounding
                acc0 = fmaf(pj, W1s[j * 64 + h0], acc0); // ascending-j fma chain
                acc1 = fmaf(pj, W1s[j * 64 + h1], acc1);
            }
            float t0 = xla_tanh(__fadd_rn(acc0, bb0));
            float t1 = xla_tanh(__fadd_rn(acc1, bb1));
            t2s[((p * 64 + h0) * 8 + k) * 2 + (m & 1)] = t0;
            t2s[((p * 64 + h1) * 8 + k) * 2 + (m & 1)] = t1;
        }
    }
    __syncthreads();

    // ---- per-thread ownership: 8 consecutive outputs o = slot*8 + r ----
    const int p    = warp >> 1;
    const int slot = (warp & 1) * 32 + lane;   // 0..63; i = slot>>3, j = slot&7
    const int obase = slot * 8;
    const float RECIP = 1.0f / TWOEPSF;        // rn(1/2e-4); unamplified use only
    float wl[8];                               // u_i*u_j*v_l/(2eps)
    {
        int i = slot >> 3, j = slot & 7;
        float wij = uvS[p * 16 + i] * uvS[p * 16 + j] * RECIP;
        #pragma unroll
        for (int l = 0; l < 8; ++l) wl[l] = wij * uvS[p * 16 + 8 + l];
    }

    float partial = 0.0f;
    const u64* t2p = reinterpret_cast<const u64*>(t2s) + p * 512;  // [h*8 + k]
    const float* stg_rd_p = cpsS + p * 576 + (slot & 0x38) * 9 + (slot & 7);
    const float* stg_rd_m = cmsS + p * 576 + (slot & 0x38) * 9 + (slot & 7);
    float* stg_wr_p = cpsS + p * 576 + slot * 9;
    float* stg_wr_m = cmsS + p * 576 + slot * 9;

    #pragma unroll
    for (int g = 0; g < 2; ++g) {           // k-groups {0..3}, {4..7}
        // ---- Phase 2 (group g): ascending-h fma chains, packed +/- ----
        u64 acc2[4][8];
        #pragma unroll
        for (int kk = 0; kk < 4; ++kk)
            #pragma unroll
            for (int r = 0; r < 8; ++r) acc2[kk][r] = 0ull;

        #pragma unroll 4
        for (int h = 0; h < HID; ++h) {
            const float4* w2q = (const float4*)(W2s + h * 512 + obase);
            float4 wa = w2q[0], wb = w2q[1];
            u64 w2d[8];
            w2d[0] = pack2(wa.x, wa.x); w2d[1] = pack2(wa.y, wa.y);
            w2d[2] = pack2(wa.z, wa.z); w2d[3] = pack2(wa.w, wa.w);
            w2d[4] = pack2(wb.x, wb.x); w2d[5] = pack2(wb.y, wb.y);
            w2d[6] = pack2(wb.z, wb.z); w2d[7] = pack2(wb.w, wb.w);
            u64 tv[4];
            #pragma unroll
            for (int kk = 0; kk < 4; ++kk) tv[kk] = t2p[h * 8 + g * 4 + kk];
            #pragma unroll
            for (int kk = 0; kk < 4; ++kk)
                #pragma unroll
                for (int r = 0; r < 8; ++r)
                    asm("fma.rn.f32x2 %0, %1, %2, %0;"
                        : "+l"(acc2[kk][r]) : "l"(tv[kk]), "l"(w2d[r]));
        }
        {   // + b2: one rounded add per element
            const float4* b2q = (const float4*)(b2s + obase);
            float4 ba = b2q[0], bb = b2q[1];
            float bv[8] = {ba.x, ba.y, ba.z, ba.w, bb.x, bb.y, bb.z, bb.w};
            #pragma unroll
            for (int r = 0; r < 8; ++r) {
                u64 bb2 = pack2(bv[r], bv[r]);
                #pragma unroll
                for (int kk = 0; kk < 4; ++kk)
                    asm("add.rn.f32x2 %0, %1, %2;"
                        : "=l"(acc2[kk][r]) : "l"(acc2[kk][r]), "l"(bb2));
            }
        }

        // ---- Phase 3 (group g): per-k symmetrize (own regs + smem transpose), FD ----
        #pragma unroll
        for (int kk = 0; kk < 4; ++kk) {
            const int k = g * 4 + kk;
            float clo[8], chi[8];
            #pragma unroll
            for (int r = 0; r < 8; ++r) {
                asm("mov.b64 {%0,%1}, %2;"
                    : "=f"(clo[r]), "=f"(chi[r]) : "l"(acc2[kk][r]));
                stg_wr_p[r] = clo[r];          // conflict-free: 9*slot mod 32 unique
                stg_wr_m[r] = chi[r];
            }
            __syncthreads();
            const float vk = uvS[p * 16 + 8 + k];
            float sk = 0.0f;
            #pragma unroll
            for (int l = 0; l < 8; ++l) {
                if (l == k) continue;          // (1 - eye) mask on (k,l)
                float tp = stg_rd_p[l * 9];    // c(i,l,j) at +eps, conflict-free
                float tm = stg_rd_m[l * 9];
                float gp = 0.5f * __fadd_rn(clo[l], tp);   // Gamma+ (rounded add)
                float gm = 0.5f * __fadd_rn(chi[l], tm);   // Gamma-
                sk = fmaf(wl[l], __fsub_rn(gp, gm), sk);
            }
            partial = fmaf(vk, sk, partial);
            __syncthreads();
        }
    }

    // ---- reduce 64 threads per point, finalize ----
    #pragma unroll
    for (int s = 16; s; s >>= 1) partial += __shfl_xor_sync(0xffffffffu, partial, s);
    if (lane == 0) redS[warp] = partial;
    __syncthreads();
    if (tid < PTS_PER_CTA) {
        float R = redS[2 * tid] + redS[2 * tid + 1];
        const int n = n0 + tid;
        const float* g = gS + (n & 7) * 64;
        const float* uL = uvS + tid * 16;
        const float* vL = uvS + tid * 16 + 8;
        float guu = 0.0f, gvv = 0.0f, guv = 0.0f;
        #pragma unroll
        for (int i = 0; i < D; ++i) {
            float gu = 0.0f, gv = 0.0f;
            #pragma unroll
            for (int j = 0; j < D; ++j) {
                float ge = g[i * 8 + j];
                gu = fmaf(ge, uL[j], gu);
                gv = fmaf(ge, vL[j], gv);
            }
            guu = fmaf(uL[i], gu, guu);
            gvv = fmaf(vL[i], gv, gvv);
            guv = fmaf(uL[i], gv, guv);
        }
        float den = fmaxf(guu * gvv - guv * guv, 1e-8f);
        out[n] = R / den;
    }
}

extern "C" void kernel_launch(void* const* d_in, const int* in_sizes, int n_in,
                              void* d_out, int out_size)
{
    const float* positions = (const float*)d_in[0];
    const float* u         = (const float*)d_in[1];
    const float* v         = (const float*)d_in[2];
    const float* chol      = (const float*)d_in[3];
    const float* W1        = (const float*)d_in[4];
    const float* b1        = (const float*)d_in[5];
    const float* W2        = (const float*)d_in[6];
    const float* b2        = (const float*)d_in[7];
    float* out = (float*)d_out;

    cudaFuncSetAttribute(rg_kernel, cudaFuncAttributeMaxDynamicSharedMemorySize,
                         SMEM_BYTES);
    rg_kernel<<<GRID, THREADS, SMEM_BYTES>>>(positions, u, v, chol,
                                             W1, b1, W2, b2, out);
}